// round 16
// baseline (speedup 1.0000x reference)
#include <cuda_runtime.h>
#include <cuda_fp16.h>
#include <cstdint>

#define BATCH 128
#define N0 2048
#define N1 2048
#define N2 512
#define K0 1024
#define KF 4096            // hi|lo concatenated K dimension (weights)
#define KS 2048            // spike storage stride
#define ALPHA_C 0.9f
#define BETA_C  0.85f
#define TSTEPS 50
#define NCTA 128
#define PTHREADS 512       // persistent kernel threads

// ---- H0 standalone GEMM staging ----
#define RS 40
#define STAGE_H (128 * RS)
#define H0_SMEM_BYTES (3 * STAGE_H * 2 * 2)      // 61440

// ---- persistent kernel smem layout (halves) ----
#define W1_RS 520                                 // 512 + 8 pad (128-wide tile, K_loc 512)
#define W2_RS 264                                 // 256 + 8 pad (64-wide tile, K_loc 256)
#define A_RS  72                                  // 64 + 8 pad
#define A_STG (128 * A_RS)                        // 9216 halves / stage
#define SW1_OFF 0
#define SW2_OFF (128 * W1_RS)                     // 66560
#define SA_OFF  (SW2_OFF + 64 * W2_RS)            // 83456
#define PERS_SMEM_BYTES ((SA_OFF + 3 * A_STG) * 2)  // 222208 B

// ---------------- static device scratch ----------------
__device__ float g_H0[BATCH * N0];
__device__ float g_m0[BATCH * N0];
__device__ float g_s1[BATCH * N1];
__device__ float g_m1[BATCH * N1];
__device__ float g_s2[BATCH * N2];
__device__ float g_m2[BATCH * N2];
__device__ __half g_spk0h[2][BATCH * KS];  // layer0 spikes fp16, double-buffered
__device__ __half g_spk1h[BATCH * KS];     // layer1 spikes fp16
__device__ __half g_inh[BATCH * KF];       // input ext: [hi | lo | hi | 0]
__device__ __half g_W0Th[N0 * KF];         // [n][k]: [hiW | hiW | loW | 0]
__device__ __half g_W1Th[N1 * KF];         // [n][k]: k<2048 hi, k>=2048 lo
__device__ __half g_W2Th[N2 * KF];
__device__ float g_p1[8 * BATCH * N1];     // split-K partials (H0 GEMM 8 / GEMM1 8)
__device__ float g_p2[16 * BATCH * N2];    // split-K partials GEMM2 (16)
__device__ unsigned g_ctr;                 // grid barrier counter

// ---------------- PTX helpers ----------------
__device__ __forceinline__ uint32_t smem_u32(const void* p) {
    uint32_t a;
    asm("{ .reg .u64 t; cvta.to.shared.u64 t, %1; cvt.u32.u64 %0, t; }" : "=r"(a) : "l"(p));
    return a;
}
__device__ __forceinline__ void cp16(uint32_t dst, const void* src) {
    asm volatile("cp.async.cg.shared.global [%0], [%1], 16;" :: "r"(dst), "l"(src));
}
__device__ __forceinline__ void ldmx4(uint32_t addr, uint32_t& r0, uint32_t& r1,
                                      uint32_t& r2, uint32_t& r3) {
    asm volatile("ldmatrix.sync.aligned.m8n8.x4.shared.b16 {%0,%1,%2,%3}, [%4];"
                 : "=r"(r0), "=r"(r1), "=r"(r2), "=r"(r3) : "r"(addr));
}
__device__ __forceinline__ void mma16816(float* d, const uint32_t* a, const uint32_t* b) {
    asm volatile(
        "mma.sync.aligned.m16n8k16.row.col.f32.f16.f16.f32 "
        "{%0,%1,%2,%3}, {%4,%5,%6,%7}, {%8,%9}, {%0,%1,%2,%3};"
        : "+f"(d[0]), "+f"(d[1]), "+f"(d[2]), "+f"(d[3])
        : "r"(a[0]), "r"(a[1]), "r"(a[2]), "r"(a[3]), "r"(b[0]), "r"(b[1]));
}
__device__ __forceinline__ unsigned ld_acq(const unsigned* p) {
    unsigned v;
    asm volatile("ld.global.acquire.gpu.u32 %0, [%1];" : "=r"(v) : "l"(p) : "memory");
    return v;
}
__device__ __forceinline__ void red_rel_add(unsigned* p, unsigned v) {
    asm volatile("red.release.gpu.global.add.u32 [%0], %1;" :: "l"(p), "r"(v) : "memory");
}

// ---------------- grid-wide barrier ----------------
__device__ __forceinline__ void gridbar(unsigned target) {
    __syncthreads();
    if (threadIdx.x == 0) {
        red_rel_add(&g_ctr, 1u);
        while (ld_acq(&g_ctr) < target) { }
    }
    __syncthreads();
}

// ---------------- A-stage loader (128 rows x 64 k, triple-buffered ring, 512 thr) ----------------
__device__ __forceinline__ void stage_A(const __half* __restrict__ A, __half* __restrict__ sA, int s) {
    const int tid = threadIdx.x;
    const int buf = s % 3;
    const int k0 = s * 64;
    __half* d = sA + buf * A_STG;
    #pragma unroll
    for (int i = 0; i < 2; i++) {
        int c = tid + i * 512;                 // 1024 16B chunks
        int r = c >> 3, j = c & 7;
        cp16(smem_u32(d + r * A_RS + j * 8), A + (size_t)r * KS + k0 + j * 8);
    }
    asm volatile("cp.async.commit_group;" ::: "memory");
}

// ---------------- resident-weight HMMA GEMM: 128x128 tile, 16 warps (4m x 4n) ----------------
template <int S, int BRS, int NFULL>
__device__ __forceinline__ void gemm_res128(const __half* __restrict__ A,
                                            const __half* __restrict__ sB,
                                            __half* __restrict__ sA,
                                            float* __restrict__ Pp,
                                            int n0, int preloaded,
                                            const __half* __restrict__ nextA2)
{
    const int tid = threadIdx.x, lane = tid & 31, wid = tid >> 5;
    const int wm = wid & 3, wn = wid >> 2;      // wm 0..3 (rows), wn 0..3 (32-col groups)

    float acc[2][4][4];
    #pragma unroll
    for (int mt = 0; mt < 2; mt++)
        #pragma unroll
        for (int nt = 0; nt < 4; nt++)
            #pragma unroll
            for (int q = 0; q < 4; q++) acc[mt][nt][q] = 0.f;

    if (preloaded < 1) stage_A(A, sA, 0);
    if (S > 1 && preloaded < 2) stage_A(A, sA, 1);

    for (int s = 0; s < S; s++) {
        if (s + 1 < S) { asm volatile("cp.async.wait_group 1;" ::: "memory"); }
        else           { asm volatile("cp.async.wait_group 0;" ::: "memory"); }
        __syncthreads();
        if (s + 2 < S) stage_A(A, sA, s + 2);

        const __half* bufA = sA + (s % 3) * A_STG;
        #pragma unroll
        for (int ks = 0; ks < 4; ks++) {
            uint32_t a[2][4], b[4][2];
            #pragma unroll
            for (int mt = 0; mt < 2; mt++) {
                int row = wm * 32 + mt * 16 + (lane & 15);
                uint32_t ad = smem_u32(bufA + row * A_RS + ks * 16 + (lane >> 4) * 8);
                ldmx4(ad, a[mt][0], a[mt][1], a[mt][2], a[mt][3]);
            }
            #pragma unroll
            for (int q = 0; q < 2; q++) {
                int nr = wn * 32 + q * 16 + (lane >> 4) * 8 + (lane & 7);
                uint32_t bd = smem_u32(sB + nr * BRS + s * 64 + ks * 16 + ((lane >> 3) & 1) * 8);
                ldmx4(bd, b[2 * q][0], b[2 * q][1], b[2 * q + 1][0], b[2 * q + 1][1]);
            }
            #pragma unroll
            for (int mt = 0; mt < 2; mt++)
                #pragma unroll
                for (int nt = 0; nt < 4; nt++)
                    mma16816(acc[mt][nt], a[mt], b[nt]);
        }
    }
    __syncthreads();          // ring fully consumed

    if (nextA2) {             // prestage the next GEMM's A under our epilogue
        stage_A(nextA2, sA, 0);
        stage_A(nextA2, sA, 1);
    }

    float* Pb = Pp + n0;
    #pragma unroll
    for (int mt = 0; mt < 2; mt++) {
        int r = wm * 32 + mt * 16 + (lane >> 2);
        #pragma unroll
        for (int nt = 0; nt < 4; nt++) {
            int cc = wn * 32 + nt * 8 + (lane & 3) * 2;
            *(float2*)(Pb + (size_t)r * NFULL + cc)       = make_float2(acc[mt][nt][0], acc[mt][nt][1]);
            *(float2*)(Pb + (size_t)(r + 8) * NFULL + cc) = make_float2(acc[mt][nt][2], acc[mt][nt][3]);
        }
    }
}

// ---------------- resident-weight HMMA GEMM: 128x64 tile, 16 warps (4m x 4n, 16 cols/warp) ----------------
template <int S, int BRS, int NFULL>
__device__ __forceinline__ void gemm_res64(const __half* __restrict__ A,
                                           const __half* __restrict__ sB,
                                           __half* __restrict__ sA,
                                           float* __restrict__ Pp,
                                           int n0, int preloaded)
{
    const int tid = threadIdx.x, lane = tid & 31, wid = tid >> 5;
    const int wm = wid & 3, wn = wid >> 2;          // wn 0..3: 16-col groups

    float acc[2][2][4];
    #pragma unroll
    for (int mt = 0; mt < 2; mt++)
        #pragma unroll
        for (int nt = 0; nt < 2; nt++)
            #pragma unroll
            for (int q = 0; q < 4; q++) acc[mt][nt][q] = 0.f;

    if (preloaded < 1) stage_A(A, sA, 0);
    if (S > 1 && preloaded < 2) stage_A(A, sA, 1);

    for (int s = 0; s < S; s++) {
        if (s + 1 < S) { asm volatile("cp.async.wait_group 1;" ::: "memory"); }
        else           { asm volatile("cp.async.wait_group 0;" ::: "memory"); }
        __syncthreads();
        if (s + 2 < S) stage_A(A, sA, s + 2);

        const __half* bufA = sA + (s % 3) * A_STG;
        #pragma unroll
        for (int ks = 0; ks < 4; ks++) {
            uint32_t a[2][4], b[2][2];
            #pragma unroll
            for (int mt = 0; mt < 2; mt++) {
                int row = wm * 32 + mt * 16 + (lane & 15);
                uint32_t ad = smem_u32(bufA + row * A_RS + ks * 16 + (lane >> 4) * 8);
                ldmx4(ad, a[mt][0], a[mt][1], a[mt][2], a[mt][3]);
            }
            {
                int nr = wn * 16 + (lane >> 4) * 8 + (lane & 7);
                uint32_t bd = smem_u32(sB + nr * BRS + s * 64 + ks * 16 + ((lane >> 3) & 1) * 8);
                ldmx4(bd, b[0][0], b[0][1], b[1][0], b[1][1]);
            }
            #pragma unroll
            for (int mt = 0; mt < 2; mt++)
                #pragma unroll
                for (int nt = 0; nt < 2; nt++)
                    mma16816(acc[mt][nt], a[mt], b[nt]);
        }
    }
    __syncthreads();

    float* Pb = Pp + n0;
    #pragma unroll
    for (int mt = 0; mt < 2; mt++) {
        int r = wm * 32 + mt * 16 + (lane >> 2);
        #pragma unroll
        for (int nt = 0; nt < 2; nt++) {
            int cc = wn * 16 + nt * 8 + (lane & 3) * 2;
            *(float2*)(Pb + (size_t)r * NFULL + cc)       = make_float2(acc[mt][nt][0], acc[mt][nt][1]);
            *(float2*)(Pb + (size_t)(r + 8) * NFULL + cc) = make_float2(acc[mt][nt][2], acc[mt][nt][3]);
        }
    }
}

// ---------------- fully-staged GEMM body (used once for H0, 256 thr, KF strides) ----------------
template <int KLOC, int NFULL>
__device__ __forceinline__ void gemm_body(const __half* __restrict__ A,
                                          const __half* __restrict__ B,
                                          float* __restrict__ Pp,
                                          int n0, int kbase,
                                          __half* sAb, __half* sBb)
{
    constexpr int S = KLOC / 32;
    const int tid = threadIdx.x, lane = tid & 31, wid = tid >> 5;
    const int wm = wid & 3, wn = wid >> 2;

    float acc[2][8][4];
    #pragma unroll
    for (int mt = 0; mt < 2; mt++)
        #pragma unroll
        for (int nt = 0; nt < 8; nt++)
            #pragma unroll
            for (int q = 0; q < 4; q++) acc[mt][nt][q] = 0.f;

    auto load_stage = [&](int s) {
        const int buf = s % 3;
        const int k0 = kbase + s * 32;
        __half* dA = sAb + buf * STAGE_H;
        __half* dB = sBb + buf * STAGE_H;
        {
            int r = tid >> 1, sub = (tid & 1) * 2;
            cp16(smem_u32(dA + r * RS + sub * 8),     A + (size_t)r * KF + k0 + sub * 8);
            cp16(smem_u32(dA + r * RS + sub * 8 + 8), A + (size_t)r * KF + k0 + sub * 8 + 8);
            cp16(smem_u32(dB + r * RS + sub * 8),     B + (size_t)(n0 + r) * KF + k0 + sub * 8);
            cp16(smem_u32(dB + r * RS + sub * 8 + 8), B + (size_t)(n0 + r) * KF + k0 + sub * 8 + 8);
        }
        asm volatile("cp.async.commit_group;" ::: "memory");
    };

    load_stage(0);
    load_stage(1);

    for (int s = 0; s < S; s++) {
        if (s + 1 < S) { asm volatile("cp.async.wait_group 1;" ::: "memory"); }
        else           { asm volatile("cp.async.wait_group 0;" ::: "memory"); }
        __syncthreads();
        if (s + 2 < S) load_stage(s + 2);

        const __half* bufA = sAb + (s % 3) * STAGE_H;
        const __half* bufB = sBb + (s % 3) * STAGE_H;
        #pragma unroll
        for (int ks = 0; ks < 2; ks++) {
            uint32_t a[2][4], b[8][2];
            #pragma unroll
            for (int mt = 0; mt < 2; mt++) {
                int row = wm * 32 + mt * 16 + (lane & 15);
                uint32_t ad = smem_u32(bufA + row * RS + ks * 16 + (lane >> 4) * 8);
                ldmx4(ad, a[mt][0], a[mt][1], a[mt][2], a[mt][3]);
            }
            #pragma unroll
            for (int q = 0; q < 4; q++) {
                int nr = wn * 64 + q * 16 + (lane >> 4) * 8 + (lane & 7);
                uint32_t bd = smem_u32(bufB + nr * RS + ks * 16 + ((lane >> 3) & 1) * 8);
                ldmx4(bd, b[2 * q][0], b[2 * q][1], b[2 * q + 1][0], b[2 * q + 1][1]);
            }
            #pragma unroll
            for (int mt = 0; mt < 2; mt++)
                #pragma unroll
                for (int nt = 0; nt < 8; nt++)
                    mma16816(acc[mt][nt], a[mt], b[nt]);
        }
    }

    float* Pb = Pp + n0;
    #pragma unroll
    for (int mt = 0; mt < 2; mt++) {
        int r = wm * 32 + mt * 16 + (lane >> 2);
        #pragma unroll
        for (int nt = 0; nt < 8; nt++) {
            int cc = wn * 64 + nt * 8 + (lane & 3) * 2;
            *(float2*)(Pb + (size_t)r * NFULL + cc)       = make_float2(acc[mt][nt][0], acc[mt][nt][1]);
            *(float2*)(Pb + (size_t)(r + 8) * NFULL + cc) = make_float2(acc[mt][nt][2], acc[mt][nt][3]);
        }
    }
}

template <int KLOC, int NFULL>
__global__ void __launch_bounds__(256) gemm_mma(const __half* __restrict__ A,
                                                const __half* __restrict__ B,
                                                float* __restrict__ P)
{
    extern __shared__ __align__(128) __half dynsm[];
    gemm_body<KLOC, NFULL>(A, B, P + (size_t)blockIdx.y * BATCH * NFULL,
                           blockIdx.x * 128, blockIdx.y * KLOC, dynsm, dynsm + 3 * STAGE_H);
}

// ---------------- elementwise helpers ----------------
__device__ __forceinline__ void f4_add(float4& a, const float4 b) {
    a.x += b.x; a.y += b.y; a.z += b.z; a.w += b.w;
}
__device__ __forceinline__ float4 f4_axpy(float al, const float4 a, const float4 b) {
    return make_float4(fmaf(al, a.x, b.x), fmaf(al, a.y, b.y), fmaf(al, a.z, b.z), fmaf(al, a.w, b.w));
}
__device__ __forceinline__ void lif_spike_reset(float4& m, float4& spk) {
    bool fx = (m.x - 1.0f) > 0.0f, fy = (m.y - 1.0f) > 0.0f;
    bool fz = (m.z - 1.0f) > 0.0f, fw = (m.w - 1.0f) > 0.0f;
    spk.x = fx ? 1.0f : 0.0f; if (fx) m.x = 0.0f;
    spk.y = fy ? 1.0f : 0.0f; if (fy) m.y = 0.0f;
    spk.z = fz ? 1.0f : 0.0f; if (fz) m.z = 0.0f;
    spk.w = fw ? 1.0f : 0.0f; if (fw) m.w = 0.0f;
}
__device__ __forceinline__ void store_spk_h(__half* base, int idx, const float4 spk) {
    __half2 p0 = __floats2half2_rn(spk.x, spk.y);
    __half2 p1 = __floats2half2_rn(spk.z, spk.w);
    unsigned long long v = (unsigned long long)(*(unsigned*)&p0)
                         | ((unsigned long long)(*(unsigned*)&p1) << 32);
    ((unsigned long long*)base)[idx] = v;
}

// ---------------- persistent loop kernel (512 threads) ----------------
__global__ void __launch_bounds__(PTHREADS, 1) persistent_loop(float* __restrict__ out)
{
    extern __shared__ __align__(128) __half dynsm[];
    __half* sW1 = dynsm + SW1_OFF;
    __half* sW2 = dynsm + SW2_OFF;
    __half* sA  = dynsm + SA_OFF;
    const int cta = blockIdx.x;
    const int tid = threadIdx.x;
    unsigned gen = 0;

    const int n0_1 = (cta & 15) * 128, kb_1 = (cta >> 4) * 512;   // GEMM1: 16 N x 8 K
    const int n0_2 = (cta & 7) * 64,   kb_2 = (cta >> 3) * 256;   // GEMM2: 8 N x 16 K
    const int ka_1 = kb_1 & (KS - 1);
    const int ka_2 = kb_2 & (KS - 1);

    // ---- load resident weight tiles once ----
    for (int c = tid; c < 8192; c += PTHREADS) {       // W1: 128 rows x 64 chunks
        int r = c >> 6, j = c & 63;
        cp16(smem_u32(sW1 + r * W1_RS + j * 8), g_W1Th + (size_t)(n0_1 + r) * KF + kb_1 + j * 8);
    }
    for (int c = tid; c < 2048; c += PTHREADS) {       // W2: 64 rows x 32 chunks
        int r = c >> 5, j = c & 31;
        cp16(smem_u32(sW2 + r * W2_RS + j * 8), g_W2Th + (size_t)(n0_2 + r) * KF + kb_2 + j * 8);
    }
    asm volatile("cp.async.commit_group;" ::: "memory");
    asm volatile("cp.async.wait_group 0;" ::: "memory");
    __syncthreads();

    // ---- preamble: H0 = sum of 8 partials; step-0 layer0 ----
    {
        int idx = cta * 512 + tid;                     // f4 over [128][2048]
        float4 h = make_float4(0.f, 0.f, 0.f, 0.f);
        #pragma unroll
        for (int ks = 0; ks < 8; ks++) f4_add(h, ((const float4*)g_p1)[(size_t)ks * 65536 + idx]);
        ((float4*)g_H0)[idx] = h;
        float4 m = h, spk;
        lif_spike_reset(m, spk);
        ((float4*)g_m0)[idx] = m;
        store_spk_h(g_spk0h[0], idx, spk);
    }
    gridbar(++gen * NCTA);

    for (int t = 0; t < TSTEPS; t++) {
        // ---- phase X: GEMM1(t) [A prestaged for t>0; prestages GEMM2 A] +
        //              GEMM2(t-1) [hot] + l0 update(t+1) ----
        gemm_res128<8, W1_RS, 2048>(g_spk0h[t & 1] + ka_1, sW1, sA,
                                    g_p1 + (size_t)(cta >> 4) * BATCH * 2048, n0_1,
                                    t > 0 ? 2 : 0,
                                    t > 0 ? g_spk1h + ka_2 : (const __half*)nullptr);
        if (t > 0)
            gemm_res64<4, W2_RS, 512>(g_spk1h + ka_2, sW2, sA,
                                      g_p2 + (size_t)(cta >> 3) * BATCH * 512, n0_2, 2);
        if (t + 1 < TSTEPS) {
            __half* spknext = g_spk0h[(t + 1) & 1];
            int idx = cta * 512 + tid;
            float4 m = f4_axpy(BETA_C, ((float4*)g_m0)[idx], ((float4*)g_H0)[idx]);
            float4 spk;
            lif_spike_reset(m, spk);
            ((float4*)g_m0)[idx] = m;
            store_spk_h(spknext, idx, spk);
        }
        gridbar(++gen * NCTA);

        // ---- phase Y: preload GEMM1(t+1) A stages ; lif1(t) ; lif2(t-1) ----
        if (t + 1 < TSTEPS) {
            const __half* An = g_spk0h[(t + 1) & 1] + ka_1;   // sealed at X(t) barrier
            stage_A(An, sA, 0);
            stage_A(An, sA, 1);
        }
        {
            int idx = cta * 512 + tid;
            float4 h = make_float4(0.f, 0.f, 0.f, 0.f);
            #pragma unroll
            for (int ks = 0; ks < 8; ks++) f4_add(h, ((const float4*)g_p1)[(size_t)ks * 65536 + idx]);
            float4 s = f4_axpy(ALPHA_C, ((float4*)g_s1)[idx], h);
            float4 m = f4_axpy(BETA_C, ((float4*)g_m1)[idx], s);
            float4 spk;
            lif_spike_reset(m, spk);
            ((float4*)g_s1)[idx] = s;
            ((float4*)g_m1)[idx] = m;
            store_spk_h(g_spk1h, idx, spk);
        }
        if (t > 0 && tid < 128) {
            int idx = cta * 128 + tid;                         // f4 over [128][512]
            float4 h = make_float4(0.f, 0.f, 0.f, 0.f);
            #pragma unroll
            for (int ks = 0; ks < 16; ks++) f4_add(h, ((const float4*)g_p2)[(size_t)ks * 16384 + idx]);
            float4 s = f4_axpy(ALPHA_C, ((float4*)g_s2)[idx], h);
            float4 m = f4_axpy(BETA_C, ((float4*)g_m2)[idx], s);   // output layer: no reset
            ((float4*)g_s2)[idx] = s;
            ((float4*)g_m2)[idx] = m;
        }
        gridbar(++gen * NCTA);
    }

    // ---- tail: GEMM2(T-1), then final lif2 + output ----
    gemm_res64<4, W2_RS, 512>(g_spk1h + ka_2, sW2, sA,
                              g_p2 + (size_t)(cta >> 3) * BATCH * 512, n0_2, 0);
    gridbar(++gen * NCTA);

    if (tid < 128) {
        int idx = cta * 128 + tid;
        float4 h = make_float4(0.f, 0.f, 0.f, 0.f);
        #pragma unroll
        for (int ks = 0; ks < 16; ks++) f4_add(h, ((const float4*)g_p2)[(size_t)ks * 16384 + idx]);
        float4 s = f4_axpy(ALPHA_C, ((float4*)g_s2)[idx], h);
        float4 m = f4_axpy(BETA_C, ((float4*)g_m2)[idx], s);
        ((float4*)out)[idx] = m;
    }
}

// ---------------- one-time prep kernels ----------------
__global__ void prep1(const float* __restrict__ inp)
{
    int g = blockIdx.x * blockDim.x + threadIdx.x;     // < 131072
    int m = g >> 10, k = g & 1023;
    float v = inp[g];
    __half hi = __float2half_rn(v);
    __half lo = __float2half_rn(v - __half2float(hi));
    size_t row = (size_t)m * KF;
    g_inh[row + k] = hi;
    g_inh[row + 1024 + k] = lo;
    g_inh[row + 2048 + k] = hi;
    g_inh[row + 3072 + k] = __float2half_rn(0.f);

    float4 z = make_float4(0.f, 0.f, 0.f, 0.f);
    if (g < 65536) { ((float4*)g_s1)[g] = z; ((float4*)g_m1)[g] = z; }
    if (g < 16384) { ((float4*)g_s2)[g] = z; ((float4*)g_m2)[g] = z; }
    if (g == 0) g_ctr = 0u;
}

__global__ void conv_w(const float* __restrict__ W, __half* __restrict__ WT, int N)
{
    __shared__ float t[32][33];
    const int k0 = blockIdx.x * 32, nb = blockIdx.y * 32;
    const int tx = threadIdx.x, ty = threadIdx.y;
    for (int i = ty; i < 32; i += 8)
        t[i][tx] = W[(size_t)(k0 + i) * N + nb + tx];
    __syncthreads();
    if (tx < 16) {
        for (int n2 = ty; n2 < 32; n2 += 8) {
            float w0 = t[2 * tx][n2], w1 = t[2 * tx + 1][n2];
            __half h0 = __float2half_rn(w0), h1 = __float2half_rn(w1);
            __half l0 = __float2half_rn(w0 - __half2float(h0));
            __half l1 = __float2half_rn(w1 - __half2float(h1));
            size_t row = (size_t)(nb + n2) * KF;
            ((__half2*)(WT + row + k0))[tx]        = __halves2half2(h0, h1);
            ((__half2*)(WT + row + 2048 + k0))[tx] = __halves2half2(l0, l1);
        }
    }
}

__global__ void conv_w0(const float* __restrict__ W, __half* __restrict__ WT)
{
    __shared__ float t[32][33];
    const int k0 = blockIdx.x * 32, nb = blockIdx.y * 32;
    const int tx = threadIdx.x, ty = threadIdx.y;
    for (int i = ty; i < 32; i += 8)
        t[i][tx] = W[(size_t)(k0 + i) * 2048 + nb + tx];
    __syncthreads();
    if (tx < 16) {
        for (int n2 = ty; n2 < 32; n2 += 8) {
            float w0 = t[2 * tx][n2], w1 = t[2 * tx + 1][n2];
            __half h0 = __float2half_rn(w0), h1 = __float2half_rn(w1);
            __half l0 = __float2half_rn(w0 - __half2float(h0));
            __half l1 = __float2half_rn(w1 - __half2float(h1));
            size_t row = (size_t)(nb + n2) * KF;
            __half2 hh = __halves2half2(h0, h1);
            ((__half2*)(WT + row + k0))[tx]        = hh;                        // seg0: hi
            ((__half2*)(WT + row + 1024 + k0))[tx] = hh;                        // seg1: hi
            ((__half2*)(WT + row + 2048 + k0))[tx] = __halves2half2(l0, l1);    // seg2: lo
            ((__half2*)(WT + row + 3072 + k0))[tx] = __halves2half2(__float2half_rn(0.f), __float2half_rn(0.f));
        }
    }
}

// ---------------- launch ----------------
extern "C" void kernel_launch(void* const* d_in, const int* in_sizes, int n_in,
                              void* d_out, int out_size)
{
    const float* inp = nullptr; const float* W0 = nullptr;
    const float* W1 = nullptr;  const float* W2 = nullptr;
    for (int i = 0; i < n_in; i++) {
        switch (in_sizes[i]) {
            case BATCH * K0: inp = (const float*)d_in[i]; break;
            case K0 * N0:    W0  = (const float*)d_in[i]; break;
            case 2048 * N1:  W1  = (const float*)d_in[i]; break;
            case 2048 * N2:  W2  = (const float*)d_in[i]; break;
        }
    }

    float* p1;
    __half *inh, *w0t, *w1t, *w2t;
    cudaGetSymbolAddress((void**)&p1,  g_p1);
    cudaGetSymbolAddress((void**)&inh, g_inh);
    cudaGetSymbolAddress((void**)&w0t, g_W0Th);
    cudaGetSymbolAddress((void**)&w1t, g_W1Th);
    cudaGetSymbolAddress((void**)&w2t, g_W2Th);

    static bool attr_done = false;
    if (!attr_done) {
        cudaFuncSetAttribute(gemm_mma<512, 2048>, cudaFuncAttributeMaxDynamicSharedMemorySize, H0_SMEM_BYTES);
        cudaFuncSetAttribute(persistent_loop, cudaFuncAttributeMaxDynamicSharedMemorySize, PERS_SMEM_BYTES);
        attr_done = true;
    }

    prep1<<<512, 256>>>(inp);                                       // #1
    conv_w0<<<dim3(32, 64), dim3(32, 8)>>>(W0, w0t);                // #2
    conv_w<<<dim3(64, 64), dim3(32, 8)>>>(W1, w1t, N1);             // #3
    conv_w<<<dim3(64, 16), dim3(32, 8)>>>(W2, w2t, N2);             // #4
    gemm_mma<512, 2048><<<dim3(16, 8), 256, H0_SMEM_BYTES>>>(inh, w0t, p1);  // #5
    persistent_loop<<<NCTA, PTHREADS, PERS_SMEM_BYTES>>>((float*)d_out); // #6
}